// round 1
// baseline (speedup 1.0000x reference)
#include <cuda_runtime.h>

// ---- problem constants ----
#define B_    8
#define N1_   8192
#define N2_   2048
#define C1_   128
#define C2_   256
#define INCH  384
#define O1_   256
#define O2_   256

// ---- device scratch (static globals: allocation-free) ----
__device__ float g_W1eff[O1_ * INCH];
__device__ float g_b1eff[O1_];
__device__ float g_W2eff[O2_ * O1_];
__device__ float g_b2eff[O2_];
__device__ int   g_idx[B_ * N1_ * 3];
__device__ float g_wgt[B_ * N1_ * 3];
__device__ float g_P [(size_t)B_ * O1_ * N2_];   // W1[:, :256] @ feats2  (16.8 MB)
__device__ float g_h1[(size_t)B_ * O1_ * N1_];   // layer-1 activations  (64 MB)

// ============================================================
// prep: fold BN scale into weights / bias
// h = g*rs*(W x + b) + be  ->  Weff = g*rs*W, beff = g*rs*b + be
// ============================================================
__global__ void prep_kernel(const float* __restrict__ W1, const float* __restrict__ b1,
                            const float* __restrict__ g1, const float* __restrict__ be1,
                            const float* __restrict__ W2, const float* __restrict__ b2,
                            const float* __restrict__ g2, const float* __restrict__ be2) {
    const float rs = 0.99999500003749969f;  // 1/sqrt(1 + 1e-5)
    int t = blockIdx.x * blockDim.x + threadIdx.x;
    int nthr = gridDim.x * blockDim.x;
    for (int i = t; i < O1_ * INCH; i += nthr) g_W1eff[i] = W1[i] * g1[i / INCH] * rs;
    for (int i = t; i < O2_ * O1_;  i += nthr) g_W2eff[i] = W2[i] * g2[i / O1_] * rs;
    for (int i = t; i < O1_; i += nthr) g_b1eff[i] = g1[i] * rs * b1[i] + be1[i];
    for (int i = t; i < O2_; i += nthr) g_b2eff[i] = g2[i] * rs * b2[i] + be2[i];
}

// ============================================================
// kNN: for each xyz1 point, 3 nearest xyz2 points + inv-dist weights
// ============================================================
__global__ void __launch_bounds__(256) knn_kernel(const float* __restrict__ xyz1,
                                                  const float* __restrict__ xyz2) {
    __shared__ float sx[N2_], sy[N2_], sz[N2_], sq[N2_];
    int b = blockIdx.y;
    const float* q = xyz2 + (size_t)b * N2_ * 3;
    for (int i = threadIdx.x; i < N2_; i += 256) {
        float ax = q[i * 3 + 0], ay = q[i * 3 + 1], az = q[i * 3 + 2];
        sx[i] = ax; sy[i] = ay; sz[i] = az;
        sq[i] = ax * ax + ay * ay + az * az;
    }
    __syncthreads();

    int p = blockIdx.x * 256 + threadIdx.x;
    const float* pp = xyz1 + ((size_t)b * N1_ + p) * 3;
    float x = pp[0], y = pp[1], z = pp[2];
    float p2 = x * x + y * y + z * z;

    float d0 = 3.4e38f, d1 = 3.4e38f, d2 = 3.4e38f;
    int   j0 = 0, j1 = 0, j2 = 0;
    #pragma unroll 4
    for (int m = 0; m < N2_; m++) {
        float dot = x * sx[m] + y * sy[m] + z * sz[m];
        float dd  = (p2 + sq[m]) - 2.0f * dot;   // reference's |p|^2+|q|^2-2pq
        if (dd < d2) {
            if (dd < d1) {
                d2 = d1; j2 = j1;
                if (dd < d0) { d1 = d0; j1 = j0; d0 = dd; j0 = m; }
                else         { d1 = dd; j1 = m; }
            } else { d2 = dd; j2 = m; }
        }
    }
    float r0 = sqrtf(fmaxf(d0, 0.f));
    float r1 = sqrtf(fmaxf(d1, 0.f));
    float r2 = sqrtf(fmaxf(d2, 0.f));
    float w0 = 1.0f / fmaxf(r0, 1e-8f);
    float w1 = 1.0f / fmaxf(r1, 1e-8f);
    float w2 = 1.0f / fmaxf(r2, 1e-8f);
    float inv = 1.0f / (w0 + w1 + w2);

    size_t base = ((size_t)b * N1_ + p) * 3;
    g_idx[base + 0] = j0; g_idx[base + 1] = j1; g_idx[base + 2] = j2;
    g_wgt[base + 0] = w0 * inv; g_wgt[base + 1] = w1 * inv; g_wgt[base + 2] = w2 * inv;
}

// ============================================================
// Shared 128x128x16 fp32 SGEMM core. A: MxK row-major (lda), B: KxN (ldb),
// C: MxN (ldc). 256 threads, 8x8 per thread.
// EPI 0: plain store. EPI 1: += 3-NN gather of P, +bias, relu. EPI 2: +bias, relu.
// ============================================================
template <int EPI>
__device__ __forceinline__ void sgemm_core(
    const float* __restrict__ A, int lda,
    const float* __restrict__ Bb, int ldb,
    float* __restrict__ Cb, int ldc, int K,
    const float* __restrict__ bias,
    const float* __restrict__ Pb,
    const int* __restrict__ idxb,
    const float* __restrict__ wb) {

    __shared__ float As[16][128];
    __shared__ float Bs[16][128];

    const int tid = threadIdx.x;
    const int m0 = (tid >> 4) * 8;
    const int n0 = (tid & 15) * 8;
    const int blockM = blockIdx.y * 128;
    const int blockN = blockIdx.x * 128;

    float acc[8][8];
    #pragma unroll
    for (int i = 0; i < 8; i++)
        #pragma unroll
        for (int j = 0; j < 8; j++) acc[i][j] = 0.f;

    const int aRow = tid >> 2;
    const int aCol = (tid & 3) << 2;
    const int bRow = tid >> 5;
    const int bCol = (tid & 31) << 2;

    for (int k0 = 0; k0 < K; k0 += 16) {
        #pragma unroll
        for (int r = 0; r < 2; r++) {
            int m = aRow + r * 64;
            float4 v = *(const float4*)(A + (size_t)(blockM + m) * lda + (k0 + aCol));
            As[aCol + 0][m] = v.x; As[aCol + 1][m] = v.y;
            As[aCol + 2][m] = v.z; As[aCol + 3][m] = v.w;
        }
        #pragma unroll
        for (int r = 0; r < 2; r++) {
            int kk = bRow + r * 8;
            *(float4*)(&Bs[kk][bCol]) =
                *(const float4*)(Bb + (size_t)(k0 + kk) * ldb + blockN + bCol);
        }
        __syncthreads();

        #pragma unroll
        for (int k = 0; k < 16; k++) {
            float a[8], bv[8];
            #pragma unroll
            for (int i = 0; i < 8; i++) a[i] = As[k][m0 + i];
            #pragma unroll
            for (int j = 0; j < 8; j++) bv[j] = Bs[k][n0 + j];
            #pragma unroll
            for (int i = 0; i < 8; i++)
                #pragma unroll
                for (int j = 0; j < 8; j++)
                    acc[i][j] = fmaf(a[i], bv[j], acc[i][j]);
        }
        __syncthreads();
    }

    if (EPI == 1) {
        // add interpolated contribution: sum_k w_k * P[o, idx_k]
        #pragma unroll
        for (int j = 0; j < 8; j++) {
            int n = blockN + n0 + j;
            size_t kb = (size_t)n * 3;
            int   i0 = idxb[kb], i1 = idxb[kb + 1], i2 = idxb[kb + 2];
            float w0 = wb[kb],   w1 = wb[kb + 1],   w2 = wb[kb + 2];
            #pragma unroll
            for (int i = 0; i < 8; i++) {
                const float* Pr = Pb + (size_t)(blockM + m0 + i) * N2_;
                acc[i][j] += w0 * Pr[i0] + w1 * Pr[i1] + w2 * Pr[i2];
            }
        }
    }

    #pragma unroll
    for (int i = 0; i < 8; i++) {
        int o = blockM + m0 + i;
        float bs = (EPI == 0) ? 0.f : bias[o];
        #pragma unroll
        for (int j = 0; j < 8; j += 4) {
            float4 v;
            v.x = acc[i][j + 0] + bs;
            v.y = acc[i][j + 1] + bs;
            v.z = acc[i][j + 2] + bs;
            v.w = acc[i][j + 3] + bs;
            if (EPI != 0) {
                v.x = fmaxf(v.x, 0.f); v.y = fmaxf(v.y, 0.f);
                v.z = fmaxf(v.z, 0.f); v.w = fmaxf(v.w, 0.f);
            }
            *(float4*)(Cb + (size_t)o * ldc + blockN + n0 + j) = v;
        }
    }
}

// P[b] = W1eff[:, :256] @ feats2[b]      (256 x 2048, K=256)
__global__ void __launch_bounds__(256) gemm_P(const float* __restrict__ feats2) {
    int b = blockIdx.z;
    sgemm_core<0>(g_W1eff, INCH,
                  feats2 + (size_t)b * C2_ * N2_, N2_,
                  g_P + (size_t)b * O1_ * N2_, N2_, C2_,
                  nullptr, nullptr, nullptr, nullptr);
}

// h1[b] = relu( W1eff[:, 256:] @ feats1[b] + gather(P, idx, w) + b1eff )
__global__ void __launch_bounds__(256) gemm_1(const float* __restrict__ feats1) {
    int b = blockIdx.z;
    sgemm_core<1>(g_W1eff + C2_, INCH,
                  feats1 + (size_t)b * C1_ * N1_, N1_,
                  g_h1 + (size_t)b * O1_ * N1_, N1_, C1_,
                  g_b1eff,
                  g_P + (size_t)b * O1_ * N2_,
                  g_idx + (size_t)b * N1_ * 3,
                  g_wgt + (size_t)b * N1_ * 3);
}

// out[b] = relu( W2eff @ h1[b] + b2eff )
__global__ void __launch_bounds__(256) gemm_2(float* __restrict__ out) {
    int b = blockIdx.z;
    sgemm_core<2>(g_W2eff, O1_,
                  g_h1 + (size_t)b * O1_ * N1_, N1_,
                  out + (size_t)b * O2_ * N1_, N1_, O1_,
                  g_b2eff, nullptr, nullptr, nullptr);
}

// ============================================================
extern "C" void kernel_launch(void* const* d_in, const int* in_sizes, int n_in,
                              void* d_out, int out_size) {
    const float* xyz1   = (const float*)d_in[0];
    const float* xyz2   = (const float*)d_in[1];
    const float* feats1 = (const float*)d_in[2];
    const float* feats2 = (const float*)d_in[3];
    const float* W1     = (const float*)d_in[4];
    const float* b1     = (const float*)d_in[5];
    const float* g1     = (const float*)d_in[6];
    const float* be1    = (const float*)d_in[7];
    const float* W2     = (const float*)d_in[8];
    const float* b2     = (const float*)d_in[9];
    const float* g2     = (const float*)d_in[10];
    const float* be2    = (const float*)d_in[11];
    float* out = (float*)d_out;

    prep_kernel<<<64, 256>>>(W1, b1, g1, be1, W2, b2, g2, be2);
    knn_kernel<<<dim3(N1_ / 256, B_), 256>>>(xyz1, xyz2);
    gemm_P<<<dim3(N2_ / 128, O1_ / 128, B_), 256>>>(feats2);
    gemm_1<<<dim3(N1_ / 128, O1_ / 128, B_), 256>>>(feats1);
    gemm_2<<<dim3(N1_ / 128, O2_ / 128, B_), 256>>>(out);
}

// round 4
// speedup vs baseline: 1.6732x; 1.6732x over previous
#include <cuda_runtime.h>
#include <cuda_bf16.h>
#include <cstdint>

// ---- problem constants ----
#define B_    8
#define N1_   8192
#define N2_   2048
#define C1_   128
#define C2_   256
#define O1_   256
#define O2_   256

// ---- device scratch ----
__device__ __align__(16) __nv_bfloat16 g_W1a_hi[O1_ * C2_], g_W1a_lo[O1_ * C2_];
__device__ __align__(16) __nv_bfloat16 g_W1b_hi[O1_ * C1_], g_W1b_lo[O1_ * C1_];
__device__ __align__(16) __nv_bfloat16 g_W2_hi [O2_ * O1_], g_W2_lo [O2_ * O1_];
__device__ float g_b1eff[O1_], g_b2eff[O2_];
__device__ __align__(16) __nv_bfloat16 g_f1T_hi[(size_t)B_ * N1_ * C1_], g_f1T_lo[(size_t)B_ * N1_ * C1_];
__device__ __align__(16) __nv_bfloat16 g_f2T_hi[(size_t)B_ * N2_ * C2_], g_f2T_lo[(size_t)B_ * N2_ * C2_];
__device__ __align__(16) float g_PT[(size_t)B_ * N2_ * O1_];            // P^T [b][n2][o1]
__device__ __align__(16) __nv_bfloat16 g_h1T_hi[(size_t)B_ * N1_ * O1_], g_h1T_lo[(size_t)B_ * N1_ * O1_];
__device__ int   g_idx[B_ * N1_ * 3];
__device__ float g_wgt[B_ * N1_ * 3];

// ============================================================
// portable tensor-core primitives (sm_80+ ISA, OK on plain sm_103)
// ============================================================
__device__ __forceinline__ uint32_t smem_u32(const void* p) {
    uint32_t a;
    asm("{ .reg .u64 t; cvta.to.shared.u64 t, %1; cvt.u32.u64 %0, t; }" : "=r"(a) : "l"(p));
    return a;
}
__device__ __forceinline__ void ldsm4(uint32_t* r, uint32_t addr) {
    asm volatile("ldmatrix.sync.aligned.m8n8.x4.shared.b16 {%0,%1,%2,%3}, [%4];"
                 : "=r"(r[0]), "=r"(r[1]), "=r"(r[2]), "=r"(r[3]) : "r"(addr));
}
__device__ __forceinline__ void mma16816(float* c, const uint32_t* a, uint32_t b0, uint32_t b1) {
    asm volatile(
        "mma.sync.aligned.m16n8k16.row.col.f32.bf16.bf16.f32 "
        "{%0,%1,%2,%3}, {%4,%5,%6,%7}, {%8,%9}, {%0,%1,%2,%3};"
        : "+f"(c[0]), "+f"(c[1]), "+f"(c[2]), "+f"(c[3])
        : "r"(a[0]), "r"(a[1]), "r"(a[2]), "r"(a[3]), "r"(b0), "r"(b1));
}

// ============================================================
// MMA GEMM core.  D[128x128] = A(128xK, K-major) @ B(128xK, K-major)^T
// 3-term split-bf16 (hi*hi + hi*lo + lo*hi), fp32 accum.
// 512 threads = 16 warps (4x4), warp tile 32(M) x 32(N).
// EPI 0: PT store. EPI 1: gather+bias+relu+split->h1T. EPI 2: bias+relu->out.
// ============================================================
#define SLD 40   // smem row pitch (bf16 elements) for 32-wide K chunk

template <int EPI>
__device__ __forceinline__ void mma_core(
    const __nv_bfloat16* __restrict__ Ahi, const __nv_bfloat16* __restrict__ Alo, int aLd,
    const __nv_bfloat16* __restrict__ Bhi, const __nv_bfloat16* __restrict__ Blo, int bLd,
    int K,
    float* __restrict__ outP,
    const float* __restrict__ PT,
    const int* __restrict__ IX, const float* __restrict__ WG,
    const float* __restrict__ bias,
    __nv_bfloat16* __restrict__ Hhi, __nv_bfloat16* __restrict__ Hlo,
    float* __restrict__ out2,
    int Mbase, int Nbase)
{
    __shared__ __align__(16) __nv_bfloat16 sAhi[128][SLD], sAlo[128][SLD];
    __shared__ __align__(16) __nv_bfloat16 sBhi[128][SLD], sBlo[128][SLD];

    const int tid = threadIdx.x;
    const int lane = tid & 31;
    const int wid = tid >> 5;
    const int warpM = wid >> 2, warpN = wid & 3;

    float acc[2][4][4];
    #pragma unroll
    for (int i = 0; i < 2; i++)
        #pragma unroll
        for (int j = 0; j < 4; j++)
            #pragma unroll
            for (int k = 0; k < 4; k++) acc[i][j][k] = 0.f;

    const int lrow = tid >> 2;
    const int lcol = (tid & 3) * 8;

    const __nv_bfloat16* pAhi = Ahi + (size_t)(Mbase + lrow) * aLd + lcol;
    const __nv_bfloat16* pAlo = Alo + (size_t)(Mbase + lrow) * aLd + lcol;
    const __nv_bfloat16* pBhi = Bhi + (size_t)(Nbase + lrow) * bLd + lcol;
    const __nv_bfloat16* pBlo = Blo + (size_t)(Nbase + lrow) * bLd + lcol;

    // ldmatrix lane-address components
    const uint32_t aRowA = warpM * 32 + (lane & 15);
    const uint32_t aColA = (lane >> 4) << 3;
    const uint32_t bRowB = warpN * 32 + ((lane >> 4) << 3) + (lane & 7);
    const uint32_t bColB = ((lane >> 3) & 1) << 3;
    const uint32_t sAhiB = smem_u32(&sAhi[0][0]);
    const uint32_t sAloB = smem_u32(&sAlo[0][0]);
    const uint32_t sBhiB = smem_u32(&sBhi[0][0]);
    const uint32_t sBloB = smem_u32(&sBlo[0][0]);

    // preload first chunk
    uint4 rAhi = *(const uint4*)pAhi;
    uint4 rAlo = *(const uint4*)pAlo;
    uint4 rBhi = *(const uint4*)pBhi;
    uint4 rBlo = *(const uint4*)pBlo;

    for (int kb = 0; kb < K; kb += 32) {
        *(uint4*)&sAhi[lrow][lcol] = rAhi;
        *(uint4*)&sAlo[lrow][lcol] = rAlo;
        *(uint4*)&sBhi[lrow][lcol] = rBhi;
        *(uint4*)&sBlo[lrow][lcol] = rBlo;
        __syncthreads();

        int nk = (kb + 32 < K) ? kb + 32 : 0;   // clamp (dummy reload on last)
        rAhi = *(const uint4*)(pAhi + nk);
        rAlo = *(const uint4*)(pAlo + nk);
        rBhi = *(const uint4*)(pBhi + nk);
        rBlo = *(const uint4*)(pBlo + nk);

        #pragma unroll
        for (int ks = 0; ks < 2; ks++) {
            uint32_t ah[2][4], al[2][4], bh[2][4], bl[2][4];
            #pragma unroll
            for (int mi = 0; mi < 2; mi++) {
                uint32_t off = ((aRowA + mi * 16) * SLD + ks * 16 + aColA) * 2;
                ldsm4(ah[mi], sAhiB + off);
                ldsm4(al[mi], sAloB + off);
            }
            #pragma unroll
            for (int nj = 0; nj < 2; nj++) {
                uint32_t off = ((bRowB + nj * 16) * SLD + ks * 16 + bColB) * 2;
                ldsm4(bh[nj], sBhiB + off);
                ldsm4(bl[nj], sBloB + off);
            }
            #pragma unroll
            for (int mi = 0; mi < 2; mi++)
                #pragma unroll
                for (int ni = 0; ni < 4; ni++) {
                    const uint32_t* BH = bh[ni >> 1];
                    const uint32_t* BL = bl[ni >> 1];
                    uint32_t bh0 = BH[(ni & 1) * 2], bh1 = BH[(ni & 1) * 2 + 1];
                    uint32_t bl0 = BL[(ni & 1) * 2], bl1 = BL[(ni & 1) * 2 + 1];
                    mma16816(acc[mi][ni], ah[mi], bh0, bh1);   // hi*hi
                    mma16816(acc[mi][ni], ah[mi], bl0, bl1);   // hi*lo
                    mma16816(acc[mi][ni], al[mi], bh0, bh1);   // lo*hi
                }
        }
        __syncthreads();
    }

    // ---- epilogue ----
    const int r0 = lane >> 2;
    const int c0 = (lane & 3) * 2;

    if (EPI == 0) {
        #pragma unroll
        for (int mi = 0; mi < 2; mi++)
            #pragma unroll
            for (int h = 0; h < 2; h++) {
                int gm = Mbase + warpM * 32 + mi * 16 + r0 + h * 8;
                #pragma unroll
                for (int ni = 0; ni < 4; ni++) {
                    int gn = Nbase + warpN * 32 + ni * 8 + c0;
                    float2 v = make_float2(acc[mi][ni][h * 2], acc[mi][ni][h * 2 + 1]);
                    *(float2*)&outP[(size_t)gm * O1_ + gn] = v;
                }
            }
    } else if (EPI == 1) {
        #pragma unroll
        for (int mi = 0; mi < 2; mi++)
            #pragma unroll
            for (int h = 0; h < 2; h++) {
                int n = Mbase + warpM * 32 + mi * 16 + r0 + h * 8;
                int i0 = IX[n * 3], i1 = IX[n * 3 + 1], i2 = IX[n * 3 + 2];
                float w0 = WG[n * 3], w1 = WG[n * 3 + 1], w2 = WG[n * 3 + 2];
                #pragma unroll
                for (int ni = 0; ni < 4; ni++) {
                    int gn = Nbase + warpN * 32 + ni * 8 + c0;
                    float2 p0 = *(const float2*)&PT[(size_t)i0 * O1_ + gn];
                    float2 p1 = *(const float2*)&PT[(size_t)i1 * O1_ + gn];
                    float2 p2 = *(const float2*)&PT[(size_t)i2 * O1_ + gn];
                    float2 bs = *(const float2*)&bias[gn];
                    float v0 = acc[mi][ni][h * 2 + 0] + bs.x + w0 * p0.x + w1 * p1.x + w2 * p2.x;
                    float v1 = acc[mi][ni][h * 2 + 1] + bs.y + w0 * p0.y + w1 * p1.y + w2 * p2.y;
                    v0 = fmaxf(v0, 0.f); v1 = fmaxf(v1, 0.f);
                    __nv_bfloat16 h0 = __float2bfloat16(v0);
                    __nv_bfloat16 h1 = __float2bfloat16(v1);
                    __nv_bfloat162 hv; hv.x = h0; hv.y = h1;
                    __nv_bfloat162 lv;
                    lv.x = __float2bfloat16(v0 - __bfloat162float(h0));
                    lv.y = __float2bfloat16(v1 - __bfloat162float(h1));
                    size_t o = (size_t)n * O1_ + gn;
                    *(__nv_bfloat162*)&Hhi[o] = hv;
                    *(__nv_bfloat162*)&Hlo[o] = lv;
                }
            }
    } else {
        #pragma unroll
        for (int mi = 0; mi < 2; mi++)
            #pragma unroll
            for (int h = 0; h < 2; h++) {
                int gm = Mbase + warpM * 32 + mi * 16 + r0 + h * 8;   // point index n
                #pragma unroll
                for (int ni = 0; ni < 4; ni++) {
                    int gn = Nbase + warpN * 32 + ni * 8 + c0;        // o2
                    float2 bs = *(const float2*)&bias[gn];
                    float v0 = fmaxf(acc[mi][ni][h * 2 + 0] + bs.x, 0.f);
                    float v1 = fmaxf(acc[mi][ni][h * 2 + 1] + bs.y, 0.f);
                    out2[(size_t)gn * N1_ + gm] = v0;
                    out2[(size_t)(gn + 1) * N1_ + gm] = v1;
                }
            }
    }
}

// ============================================================
// GEMM wrappers (all scratch globals referenced in DEVICE code)
// ============================================================
__global__ void __launch_bounds__(512) gemmP_kernel() {
    int b = blockIdx.z;
    mma_core<0>(g_f2T_hi + (size_t)b * N2_ * C2_, g_f2T_lo + (size_t)b * N2_ * C2_, C2_,
                g_W1a_hi, g_W1a_lo, C2_, C2_,
                g_PT + (size_t)b * N2_ * O1_,
                nullptr, nullptr, nullptr, nullptr, nullptr, nullptr, nullptr,
                blockIdx.x * 128, blockIdx.y * 128);
}
__global__ void __launch_bounds__(512) gemm1_kernel() {
    int b = blockIdx.z;
    mma_core<1>(g_f1T_hi + (size_t)b * N1_ * C1_, g_f1T_lo + (size_t)b * N1_ * C1_, C1_,
                g_W1b_hi, g_W1b_lo, C1_, C1_,
                nullptr,
                g_PT + (size_t)b * N2_ * O1_,
                g_idx + (size_t)b * N1_ * 3, g_wgt + (size_t)b * N1_ * 3,
                g_b1eff,
                g_h1T_hi + (size_t)b * N1_ * O1_, g_h1T_lo + (size_t)b * N1_ * O1_,
                nullptr,
                blockIdx.x * 128, blockIdx.y * 128);
}
__global__ void __launch_bounds__(512) gemm2_kernel(float* __restrict__ out) {
    int b = blockIdx.z;
    mma_core<2>(g_h1T_hi + (size_t)b * N1_ * O1_, g_h1T_lo + (size_t)b * N1_ * O1_, O1_,
                g_W2_hi, g_W2_lo, O1_, O1_,
                nullptr, nullptr, nullptr, nullptr,
                g_b2eff, nullptr, nullptr,
                out + (size_t)b * O2_ * N1_,
                blockIdx.x * 128, blockIdx.y * 128);
}

// ============================================================
// prep: fold BN into W/b, split weights into bf16 hi/lo
// ============================================================
__global__ void prep_kernel(const float* __restrict__ W1, const float* __restrict__ b1,
                            const float* __restrict__ g1, const float* __restrict__ be1,
                            const float* __restrict__ W2, const float* __restrict__ b2,
                            const float* __restrict__ g2, const float* __restrict__ be2) {
    const float rs = 0.99999500003749969f;  // 1/sqrt(1+1e-5)
    int t = blockIdx.x * blockDim.x + threadIdx.x;
    int nt = gridDim.x * blockDim.x;
    for (int i = t; i < O1_ * C2_; i += nt) {
        int o = i / C2_;
        float w = W1[o * (C1_ + C2_) + (i % C2_)] * g1[o] * rs;
        __nv_bfloat16 hi = __float2bfloat16(w);
        g_W1a_hi[i] = hi;
        g_W1a_lo[i] = __float2bfloat16(w - __bfloat162float(hi));
    }
    for (int i = t; i < O1_ * C1_; i += nt) {
        int o = i / C1_;
        float w = W1[o * (C1_ + C2_) + C2_ + (i % C1_)] * g1[o] * rs;
        __nv_bfloat16 hi = __float2bfloat16(w);
        g_W1b_hi[i] = hi;
        g_W1b_lo[i] = __float2bfloat16(w - __bfloat162float(hi));
    }
    for (int i = t; i < O2_ * O1_; i += nt) {
        int o = i / O1_;
        float w = W2[i] * g2[o] * rs;
        __nv_bfloat16 hi = __float2bfloat16(w);
        g_W2_hi[i] = hi;
        g_W2_lo[i] = __float2bfloat16(w - __bfloat162float(hi));
    }
    for (int i = t; i < O1_; i += nt) g_b1eff[i] = g1[i] * rs * b1[i] + be1[i];
    for (int i = t; i < O2_; i += nt) g_b2eff[i] = g2[i] * rs * b2[i] + be2[i];
}

// ============================================================
// kNN (unchanged from R1 passing kernel)
// ============================================================
__global__ void __launch_bounds__(256) knn_kernel(const float* __restrict__ xyz1,
                                                  const float* __restrict__ xyz2) {
    __shared__ float sx[N2_], sy[N2_], sz[N2_], sq[N2_];
    int b = blockIdx.y;
    const float* q = xyz2 + (size_t)b * N2_ * 3;
    for (int i = threadIdx.x; i < N2_; i += 256) {
        float ax = q[i * 3 + 0], ay = q[i * 3 + 1], az = q[i * 3 + 2];
        sx[i] = ax; sy[i] = ay; sz[i] = az;
        sq[i] = ax * ax + ay * ay + az * az;
    }
    __syncthreads();

    int p = blockIdx.x * 256 + threadIdx.x;
    const float* pp = xyz1 + ((size_t)b * N1_ + p) * 3;
    float x = pp[0], y = pp[1], z = pp[2];
    float p2 = x * x + y * y + z * z;

    float d0 = 3.4e38f, d1 = 3.4e38f, d2 = 3.4e38f;
    int   j0 = 0, j1 = 0, j2 = 0;
    #pragma unroll 4
    for (int m = 0; m < N2_; m++) {
        float dot = x * sx[m] + y * sy[m] + z * sz[m];
        float dd  = (p2 + sq[m]) - 2.0f * dot;
        if (dd < d2) {
            if (dd < d1) {
                d2 = d1; j2 = j1;
                if (dd < d0) { d1 = d0; j1 = j0; d0 = dd; j0 = m; }
                else         { d1 = dd; j1 = m; }
            } else { d2 = dd; j2 = m; }
        }
    }
    float r0 = sqrtf(fmaxf(d0, 0.f));
    float r1 = sqrtf(fmaxf(d1, 0.f));
    float r2 = sqrtf(fmaxf(d2, 0.f));
    float w0 = 1.0f / fmaxf(r0, 1e-8f);
    float w1 = 1.0f / fmaxf(r1, 1e-8f);
    float w2 = 1.0f / fmaxf(r2, 1e-8f);
    float inv = 1.0f / (w0 + w1 + w2);

    size_t base = ((size_t)b * N1_ + p) * 3;
    g_idx[base + 0] = j0; g_idx[base + 1] = j1; g_idx[base + 2] = j2;
    g_wgt[base + 0] = w0 * inv; g_wgt[base + 1] = w1 * inv; g_wgt[base + 2] = w2 * inv;
}

// ============================================================
// transpose + hi/lo split, concrete kernels (globals referenced in
// device code only — fixes the R3 host-shadow-pointer bug)
// ============================================================
__device__ __forceinline__ void tsplit_body(const float* __restrict__ src,
                                            __nv_bfloat16* __restrict__ dhi,
                                            __nv_bfloat16* __restrict__ dlo,
                                            int C, int Np) {
    __shared__ float t[32][33];
    int n0 = blockIdx.x * 32, c0 = blockIdx.y * 32, b = blockIdx.z;
    int tx = threadIdx.x, ty = threadIdx.y;
    #pragma unroll
    for (int r = 0; r < 4; r++) {
        int c = c0 + ty + r * 8;
        t[ty + r * 8][tx] = src[((size_t)b * C + c) * Np + n0 + tx];
    }
    __syncthreads();
    #pragma unroll
    for (int r = 0; r < 4; r++) {
        int n = n0 + ty + r * 8;
        int c = c0 + tx;
        float v = t[tx][ty + r * 8];
        __nv_bfloat16 hi = __float2bfloat16(v);
        size_t o = ((size_t)b * Np + n) * C + c;
        dhi[o] = hi;
        dlo[o] = __float2bfloat16(v - __bfloat162float(hi));
    }
}
__global__ void tsplit1_kernel(const float* __restrict__ feats1) {
    tsplit_body(feats1, g_f1T_hi, g_f1T_lo, C1_, N1_);
}
__global__ void tsplit2_kernel(const float* __restrict__ feats2) {
    tsplit_body(feats2, g_f2T_hi, g_f2T_lo, C2_, N2_);
}

// ============================================================
extern "C" void kernel_launch(void* const* d_in, const int* in_sizes, int n_in,
                              void* d_out, int out_size) {
    const float* xyz1   = (const float*)d_in[0];
    const float* xyz2   = (const float*)d_in[1];
    const float* feats1 = (const float*)d_in[2];
    const float* feats2 = (const float*)d_in[3];
    const float* W1     = (const float*)d_in[4];
    const float* b1     = (const float*)d_in[5];
    const float* g1     = (const float*)d_in[6];
    const float* be1    = (const float*)d_in[7];
    const float* W2     = (const float*)d_in[8];
    const float* b2     = (const float*)d_in[9];
    const float* g2     = (const float*)d_in[10];
    const float* be2    = (const float*)d_in[11];
    float* out = (float*)d_out;

    prep_kernel<<<64, 256>>>(W1, b1, g1, be1, W2, b2, g2, be2);
    knn_kernel<<<dim3(N1_ / 256, B_), 256>>>(xyz1, xyz2);
    tsplit1_kernel<<<dim3(N1_ / 32, C1_ / 32, B_), dim3(32, 8)>>>(feats1);
    tsplit2_kernel<<<dim3(N2_ / 32, C2_ / 32, B_), dim3(32, 8)>>>(feats2);
    gemmP_kernel<<<dim3(N2_ / 128, O1_ / 128, B_), 512>>>();
    gemm1_kernel<<<dim3(N1_ / 128, O1_ / 128, B_), 512>>>();
    gemm2_kernel<<<dim3(N1_ / 128, O2_ / 128, B_), 512>>>(out);
}

// round 5
// speedup vs baseline: 1.7577x; 1.0505x over previous
#include <cuda_runtime.h>
#include <cuda_bf16.h>
#include <cstdint>

// ---- problem constants ----
#define B_    8
#define N1_   8192
#define N2_   2048
#define C1_   128
#define C2_   256
#define O1_   256
#define O2_   256

// ---- device scratch ----
__device__ __align__(16) __nv_bfloat16 g_W1a_hi[O1_ * C2_], g_W1a_lo[O1_ * C2_];
__device__ __align__(16) __nv_bfloat16 g_W1b_hi[O1_ * C1_], g_W1b_lo[O1_ * C1_];
__device__ __align__(16) __nv_bfloat16 g_W2_hi [O2_ * O1_], g_W2_lo [O2_ * O1_];
__device__ float g_b1eff[O1_], g_b2eff[O2_];
__device__ __align__(16) __nv_bfloat16 g_f1T_hi[(size_t)B_ * N1_ * C1_], g_f1T_lo[(size_t)B_ * N1_ * C1_];
__device__ __align__(16) __nv_bfloat16 g_f2T_hi[(size_t)B_ * N2_ * C2_], g_f2T_lo[(size_t)B_ * N2_ * C2_];
__device__ __align__(16) float g_PT[(size_t)B_ * N2_ * O1_];      // P^T [b][n2][o1]
__device__ __align__(16) float g_h1[(size_t)B_ * N1_ * O1_];      // h1  [b][n][o1] fp32
__device__ int   g_idx[B_ * N1_ * 3];
__device__ float g_wgt[B_ * N1_ * 3];

// ============================================================
// portable tensor-core primitives
// ============================================================
__device__ __forceinline__ uint32_t smem_u32(const void* p) {
    uint32_t a;
    asm("{ .reg .u64 t; cvta.to.shared.u64 t, %1; cvt.u32.u64 %0, t; }" : "=r"(a) : "l"(p));
    return a;
}
__device__ __forceinline__ void ldsm4(uint32_t* r, uint32_t addr) {
    asm volatile("ldmatrix.sync.aligned.m8n8.x4.shared.b16 {%0,%1,%2,%3}, [%4];"
                 : "=r"(r[0]), "=r"(r[1]), "=r"(r[2]), "=r"(r[3]) : "r"(addr));
}
__device__ __forceinline__ void mma16816(float* c, const uint32_t* a, uint32_t b0, uint32_t b1) {
    asm volatile(
        "mma.sync.aligned.m16n8k16.row.col.f32.bf16.bf16.f32 "
        "{%0,%1,%2,%3}, {%4,%5,%6,%7}, {%8,%9}, {%0,%1,%2,%3};"
        : "+f"(c[0]), "+f"(c[1]), "+f"(c[2]), "+f"(c[3])
        : "r"(a[0]), "r"(a[1]), "r"(a[2]), "r"(a[3]), "r"(b0), "r"(b1));
}

// split-pack two floats -> bf16x2 hi word, bf16x2 lo word
__device__ __forceinline__ uint32_t splitpack(float a, float b, uint32_t& lo) {
    __nv_bfloat16 ha = __float2bfloat16(a), hb = __float2bfloat16(b);
    __nv_bfloat16 la = __float2bfloat16(a - __bfloat162float(ha));
    __nv_bfloat16 lb = __float2bfloat16(b - __bfloat162float(hb));
    __nv_bfloat162 H2; H2.x = ha; H2.y = hb;
    __nv_bfloat162 L2; L2.x = la; L2.y = lb;
    lo = *(uint32_t*)&L2;
    return *(uint32_t*)&H2;
}

// ============================================================
// MMA GEMM core.  D[64x128] = A(64xK) @ B(128xK)^T, K-major operands.
// 3-term split-bf16 (hi*hi + hi*lo + lo*hi), fp32 accum.
// 256 threads = 8 warps (2Mx4N), warp tile 32x32 (identical fragment
// math to the verified R4 kernel).
// A source: bf16 hi/lo pair (AFP32=0) or fp32 with on-the-fly split (AFP32=1).
// EPI 0: PT store. EPI 1: gather+bias+relu -> h1 fp32. EPI 2: bias+relu -> out.
// ============================================================
#define SLD 40   // smem row pitch (bf16 elements)

template <int EPI, int AFP32>
__device__ __forceinline__ void mma_core(
    const __nv_bfloat16* __restrict__ Ahi, const __nv_bfloat16* __restrict__ Alo,
    const float* __restrict__ A32, int aLd,
    const __nv_bfloat16* __restrict__ Bhi, const __nv_bfloat16* __restrict__ Blo, int bLd,
    int K,
    float* __restrict__ outP,
    const float* __restrict__ PT,
    const int* __restrict__ IX, const float* __restrict__ WG,
    const float* __restrict__ bias,
    float* __restrict__ H,
    float* __restrict__ out2,
    int Mbase, int Nbase)
{
    __shared__ __align__(16) __nv_bfloat16 sAhi[64][SLD],  sAlo[64][SLD];
    __shared__ __align__(16) __nv_bfloat16 sBhi[128][SLD], sBlo[128][SLD];

    const int tid = threadIdx.x;
    const int lane = tid & 31;
    const int wid = tid >> 5;
    const int warpM = wid >> 2, warpN = wid & 3;   // 2 x 4 warps

    float acc[2][4][4];
    #pragma unroll
    for (int i = 0; i < 2; i++)
        #pragma unroll
        for (int j = 0; j < 4; j++)
            #pragma unroll
            for (int k = 0; k < 4; k++) acc[i][j][k] = 0.f;

    const int lrow = tid >> 2;          // 0..63
    const int lcol = (tid & 3) * 8;     // 0,8,16,24

    const __nv_bfloat16* pAhi = Ahi + (size_t)(Mbase + lrow) * aLd + lcol;
    const __nv_bfloat16* pAlo = Alo + (size_t)(Mbase + lrow) * aLd + lcol;
    const float*         pA32 = A32 + (size_t)(Mbase + lrow) * aLd + lcol;
    const __nv_bfloat16* pBhi0 = Bhi + (size_t)(Nbase + lrow) * bLd + lcol;
    const __nv_bfloat16* pBlo0 = Blo + (size_t)(Nbase + lrow) * bLd + lcol;
    const __nv_bfloat16* pBhi1 = Bhi + (size_t)(Nbase + lrow + 64) * bLd + lcol;
    const __nv_bfloat16* pBlo1 = Blo + (size_t)(Nbase + lrow + 64) * bLd + lcol;

    // ldmatrix lane-address components (identical formulas to R4)
    const uint32_t aRowA = warpM * 32 + (lane & 15);
    const uint32_t aColA = (lane >> 4) << 3;
    const uint32_t bRowB = warpN * 32 + ((lane >> 4) << 3) + (lane & 7);
    const uint32_t bColB = ((lane >> 3) & 1) << 3;
    const uint32_t sAhiB = smem_u32(&sAhi[0][0]);
    const uint32_t sAloB = smem_u32(&sAlo[0][0]);
    const uint32_t sBhiB = smem_u32(&sBhi[0][0]);
    const uint32_t sBloB = smem_u32(&sBlo[0][0]);

    // preload chunk 0
    uint4 rA0, rA1, rBh0, rBh1, rBl0, rBl1;
    if (AFP32) { rA0 = *(const uint4*)pA32; rA1 = *(const uint4*)(pA32 + 4); }
    else       { rA0 = *(const uint4*)pAhi; rA1 = *(const uint4*)pAlo; }
    rBh0 = *(const uint4*)pBhi0; rBh1 = *(const uint4*)pBhi1;
    rBl0 = *(const uint4*)pBlo0; rBl1 = *(const uint4*)pBlo1;

    for (int kb = 0; kb < K; kb += 32) {
        if (AFP32) {
            const float* f0 = (const float*)&rA0;
            const float* f1 = (const float*)&rA1;
            uint4 hi, lo;
            hi.x = splitpack(f0[0], f0[1], lo.x);
            hi.y = splitpack(f0[2], f0[3], lo.y);
            hi.z = splitpack(f1[0], f1[1], lo.z);
            hi.w = splitpack(f1[2], f1[3], lo.w);
            *(uint4*)&sAhi[lrow][lcol] = hi;
            *(uint4*)&sAlo[lrow][lcol] = lo;
        } else {
            *(uint4*)&sAhi[lrow][lcol] = rA0;
            *(uint4*)&sAlo[lrow][lcol] = rA1;
        }
        *(uint4*)&sBhi[lrow][lcol] = rBh0;
        *(uint4*)&sBhi[lrow + 64][lcol] = rBh1;
        *(uint4*)&sBlo[lrow][lcol] = rBl0;
        *(uint4*)&sBlo[lrow + 64][lcol] = rBl1;
        __syncthreads();

        int nk = (kb + 32 < K) ? kb + 32 : 0;   // dummy reload on last iter
        if (AFP32) { rA0 = *(const uint4*)(pA32 + nk); rA1 = *(const uint4*)(pA32 + nk + 4); }
        else       { rA0 = *(const uint4*)(pAhi + nk); rA1 = *(const uint4*)(pAlo + nk); }
        rBh0 = *(const uint4*)(pBhi0 + nk); rBh1 = *(const uint4*)(pBhi1 + nk);
        rBl0 = *(const uint4*)(pBlo0 + nk); rBl1 = *(const uint4*)(pBlo1 + nk);

        #pragma unroll
        for (int ks = 0; ks < 2; ks++) {
            uint32_t ah[2][4], al[2][4], bh[2][4], bl[2][4];
            #pragma unroll
            for (int mi = 0; mi < 2; mi++) {
                uint32_t off = ((aRowA + mi * 16) * SLD + ks * 16 + aColA) * 2;
                ldsm4(ah[mi], sAhiB + off);
                ldsm4(al[mi], sAloB + off);
            }
            #pragma unroll
            for (int nj = 0; nj < 2; nj++) {
                uint32_t off = ((bRowB + nj * 16) * SLD + ks * 16 + bColB) * 2;
                ldsm4(bh[nj], sBhiB + off);
                ldsm4(bl[nj], sBloB + off);
            }
            #pragma unroll
            for (int mi = 0; mi < 2; mi++)
                #pragma unroll
                for (int ni = 0; ni < 4; ni++) {
                    const uint32_t* BH = bh[ni >> 1];
                    const uint32_t* BL = bl[ni >> 1];
                    uint32_t bh0 = BH[(ni & 1) * 2], bh1 = BH[(ni & 1) * 2 + 1];
                    uint32_t bl0 = BL[(ni & 1) * 2], bl1 = BL[(ni & 1) * 2 + 1];
                    mma16816(acc[mi][ni], ah[mi], bh0, bh1);   // hi*hi
                    mma16816(acc[mi][ni], ah[mi], bl0, bl1);   // hi*lo
                    mma16816(acc[mi][ni], al[mi], bh0, bh1);   // lo*hi
                }
        }
        __syncthreads();
    }

    // ---- epilogue ----
    const int r0 = lane >> 2;
    const int c0 = (lane & 3) * 2;

    if (EPI == 0) {
        #pragma unroll
        for (int mi = 0; mi < 2; mi++)
            #pragma unroll
            for (int h = 0; h < 2; h++) {
                int gm = Mbase + warpM * 32 + mi * 16 + r0 + h * 8;
                #pragma unroll
                for (int ni = 0; ni < 4; ni++) {
                    int gn = Nbase + warpN * 32 + ni * 8 + c0;
                    float2 v = make_float2(acc[mi][ni][h * 2], acc[mi][ni][h * 2 + 1]);
                    *(float2*)&outP[(size_t)gm * O1_ + gn] = v;
                }
            }
    } else if (EPI == 1) {
        #pragma unroll
        for (int mi = 0; mi < 2; mi++)
            #pragma unroll
            for (int h = 0; h < 2; h++) {
                int n = Mbase + warpM * 32 + mi * 16 + r0 + h * 8;
                int i0 = IX[n * 3], i1 = IX[n * 3 + 1], i2 = IX[n * 3 + 2];
                float w0 = WG[n * 3], w1 = WG[n * 3 + 1], w2 = WG[n * 3 + 2];
                #pragma unroll
                for (int ni = 0; ni < 4; ni++) {
                    int gn = Nbase + warpN * 32 + ni * 8 + c0;
                    float2 p0 = *(const float2*)&PT[(size_t)i0 * O1_ + gn];
                    float2 p1 = *(const float2*)&PT[(size_t)i1 * O1_ + gn];
                    float2 p2 = *(const float2*)&PT[(size_t)i2 * O1_ + gn];
                    float2 bs = *(const float2*)&bias[gn];
                    float v0 = acc[mi][ni][h * 2 + 0] + bs.x + w0 * p0.x + w1 * p1.x + w2 * p2.x;
                    float v1 = acc[mi][ni][h * 2 + 1] + bs.y + w0 * p0.y + w1 * p1.y + w2 * p2.y;
                    v0 = fmaxf(v0, 0.f); v1 = fmaxf(v1, 0.f);
                    *(float2*)&H[(size_t)n * O1_ + gn] = make_float2(v0, v1);
                }
            }
    } else {
        #pragma unroll
        for (int mi = 0; mi < 2; mi++)
            #pragma unroll
            for (int h = 0; h < 2; h++) {
                int gm = Mbase + warpM * 32 + mi * 16 + r0 + h * 8;   // point index n
                #pragma unroll
                for (int ni = 0; ni < 4; ni++) {
                    int gn = Nbase + warpN * 32 + ni * 8 + c0;        // o2
                    float2 bs = *(const float2*)&bias[gn];
                    float v0 = fmaxf(acc[mi][ni][h * 2 + 0] + bs.x, 0.f);
                    float v1 = fmaxf(acc[mi][ni][h * 2 + 1] + bs.y, 0.f);
                    out2[(size_t)gn * N1_ + gm] = v0;
                    out2[(size_t)(gn + 1) * N1_ + gm] = v1;
                }
            }
    }
}

// ============================================================
// GEMM wrappers (all scratch globals referenced in device code)
// ============================================================
__global__ void __launch_bounds__(256, 2) gemmP_kernel() {
    int b = blockIdx.z;
    mma_core<0, 0>(g_f2T_hi + (size_t)b * N2_ * C2_, g_f2T_lo + (size_t)b * N2_ * C2_,
                   nullptr, C2_,
                   g_W1a_hi, g_W1a_lo, C2_, C2_,
                   g_PT + (size_t)b * N2_ * O1_,
                   nullptr, nullptr, nullptr, nullptr, nullptr, nullptr,
                   blockIdx.x * 64, blockIdx.y * 128);
}
__global__ void __launch_bounds__(256, 2) gemm1_kernel() {
    int b = blockIdx.z;
    mma_core<1, 0>(g_f1T_hi + (size_t)b * N1_ * C1_, g_f1T_lo + (size_t)b * N1_ * C1_,
                   nullptr, C1_,
                   g_W1b_hi, g_W1b_lo, C1_, C1_,
                   nullptr,
                   g_PT + (size_t)b * N2_ * O1_,
                   g_idx + (size_t)b * N1_ * 3, g_wgt + (size_t)b * N1_ * 3,
                   g_b1eff,
                   g_h1 + (size_t)b * N1_ * O1_,
                   nullptr,
                   blockIdx.x * 64, blockIdx.y * 128);
}
__global__ void __launch_bounds__(256, 2) gemm2_kernel(float* __restrict__ out) {
    int b = blockIdx.z;
    mma_core<2, 1>(nullptr, nullptr,
                   g_h1 + (size_t)b * N1_ * O1_, O1_,
                   g_W2_hi, g_W2_lo, O1_, O1_,
                   nullptr, nullptr, nullptr, nullptr,
                   g_b2eff, nullptr,
                   out + (size_t)b * O2_ * N1_,
                   blockIdx.x * 64, blockIdx.y * 128);
}

// ============================================================
// prep: fold BN into W/b, split weights into bf16 hi/lo
// ============================================================
__global__ void prep_kernel(const float* __restrict__ W1, const float* __restrict__ b1,
                            const float* __restrict__ g1, const float* __restrict__ be1,
                            const float* __restrict__ W2, const float* __restrict__ b2,
                            const float* __restrict__ g2, const float* __restrict__ be2) {
    const float rs = 0.99999500003749969f;  // 1/sqrt(1+1e-5)
    int t = blockIdx.x * blockDim.x + threadIdx.x;
    int nt = gridDim.x * blockDim.x;
    for (int i = t; i < O1_ * C2_; i += nt) {
        int o = i / C2_;
        float w = W1[o * (C1_ + C2_) + (i % C2_)] * g1[o] * rs;
        __nv_bfloat16 hi = __float2bfloat16(w);
        g_W1a_hi[i] = hi;
        g_W1a_lo[i] = __float2bfloat16(w - __bfloat162float(hi));
    }
    for (int i = t; i < O1_ * C1_; i += nt) {
        int o = i / C1_;
        float w = W1[o * (C1_ + C2_) + C2_ + (i % C1_)] * g1[o] * rs;
        __nv_bfloat16 hi = __float2bfloat16(w);
        g_W1b_hi[i] = hi;
        g_W1b_lo[i] = __float2bfloat16(w - __bfloat162float(hi));
    }
    for (int i = t; i < O2_ * O1_; i += nt) {
        int o = i / O1_;
        float w = W2[i] * g2[o] * rs;
        __nv_bfloat16 hi = __float2bfloat16(w);
        g_W2_hi[i] = hi;
        g_W2_lo[i] = __float2bfloat16(w - __bfloat162float(hi));
    }
    for (int i = t; i < O1_; i += nt) g_b1eff[i] = g1[i] * rs * b1[i] + be1[i];
    for (int i = t; i < O2_; i += nt) g_b2eff[i] = g2[i] * rs * b2[i] + be2[i];
}

// ============================================================
// kNN: float4-packed candidates (1 LDS.128 per candidate)
// ============================================================
__global__ void __launch_bounds__(256) knn_kernel(const float* __restrict__ xyz1,
                                                  const float* __restrict__ xyz2) {
    __shared__ __align__(16) float4 s2[N2_];
    int b = blockIdx.y;
    const float* q = xyz2 + (size_t)b * N2_ * 3;
    for (int i = threadIdx.x; i < N2_; i += 256) {
        float ax = q[i * 3 + 0], ay = q[i * 3 + 1], az = q[i * 3 + 2];
        s2[i] = make_float4(ax, ay, az, ax * ax + ay * ay + az * az);
    }
    __syncthreads();

    int p = blockIdx.x * 256 + threadIdx.x;
    const float* pp = xyz1 + ((size_t)b * N1_ + p) * 3;
    float x = pp[0], y = pp[1], z = pp[2];
    float p2 = x * x + y * y + z * z;

    float d0 = 3.4e38f, d1 = 3.4e38f, d2 = 3.4e38f;
    int   j0 = 0, j1 = 0, j2 = 0;
    #pragma unroll 4
    for (int m = 0; m < N2_; m++) {
        float4 v = s2[m];
        float dot = x * v.x + y * v.y + z * v.z;
        float dd  = (p2 + v.w) - 2.0f * dot;   // reference's |p|^2+|q|^2-2pq
        if (dd < d2) {
            if (dd < d1) {
                d2 = d1; j2 = j1;
                if (dd < d0) { d1 = d0; j1 = j0; d0 = dd; j0 = m; }
                else         { d1 = dd; j1 = m; }
            } else { d2 = dd; j2 = m; }
        }
    }
    float r0 = sqrtf(fmaxf(d0, 0.f));
    float r1 = sqrtf(fmaxf(d1, 0.f));
    float r2 = sqrtf(fmaxf(d2, 0.f));
    float w0 = 1.0f / fmaxf(r0, 1e-8f);
    float w1 = 1.0f / fmaxf(r1, 1e-8f);
    float w2 = 1.0f / fmaxf(r2, 1e-8f);
    float inv = 1.0f / (w0 + w1 + w2);

    size_t base = ((size_t)b * N1_ + p) * 3;
    g_idx[base + 0] = j0; g_idx[base + 1] = j1; g_idx[base + 2] = j2;
    g_wgt[base + 0] = w0 * inv; g_wgt[base + 1] = w1 * inv; g_wgt[base + 2] = w2 * inv;
}

// ============================================================
// transpose + hi/lo split:  src[b][C][Np] -> dst[b][Np][C] (bf16 hi/lo)
// ============================================================
__device__ __forceinline__ void tsplit_body(const float* __restrict__ src,
                                            __nv_bfloat16* __restrict__ dhi,
                                            __nv_bfloat16* __restrict__ dlo,
                                            int C, int Np) {
    __shared__ float t[32][33];
    int n0 = blockIdx.x * 32, c0 = blockIdx.y * 32, b = blockIdx.z;
    int tx = threadIdx.x, ty = threadIdx.y;
    #pragma unroll
    for (int r = 0; r < 4; r++) {
        int c = c0 + ty + r * 8;
        t[ty + r * 8][tx] = src[((size_t)b * C + c) * Np + n0 + tx];
    }
    __syncthreads();
    #pragma unroll
    for (int r = 0; r < 4; r++) {
        int n = n0 + ty + r * 8;
        int c = c0 + tx;
        float v = t[tx][ty + r * 8];
        __nv_bfloat16 hi = __float2bfloat16(v);
        size_t o = ((size_t)b * Np + n) * C + c;
        dhi[o] = hi;
        dlo[o] = __float2bfloat16(v - __bfloat162float(hi));
    }
}
__global__ void tsplit1_kernel(const float* __restrict__ feats1) {
    tsplit_body(feats1, g_f1T_hi, g_f1T_lo, C1_, N1_);
}
__global__ void tsplit2_kernel(const float* __restrict__ feats2) {
    tsplit_body(feats2, g_f2T_hi, g_f2T_lo, C2_, N2_);
}

// ============================================================
extern "C" void kernel_launch(void* const* d_in, const int* in_sizes, int n_in,
                              void* d_out, int out_size) {
    const float* xyz1   = (const float*)d_in[0];
    const float* xyz2   = (const float*)d_in[1];
    const float* feats1 = (const float*)d_in[2];
    const float* feats2 = (const float*)d_in[3];
    const float* W1     = (const float*)d_in[4];
    const float* b1     = (const float*)d_in[5];
    const float* g1     = (const float*)d_in[6];
    const float* be1    = (const float*)d_in[7];
    const float* W2     = (const float*)d_in[8];
    const float* b2     = (const float*)d_in[9];
    const float* g2     = (const float*)d_in[10];
    const float* be2    = (const float*)d_in[11];
    float* out = (float*)d_out;

    prep_kernel<<<64, 256>>>(W1, b1, g1, be1, W2, b2, g2, be2);
    knn_kernel<<<dim3(N1_ / 256, B_), 256>>>(xyz1, xyz2);
    tsplit1_kernel<<<dim3(N1_ / 32, C1_ / 32, B_), dim3(32, 8)>>>(feats1);
    tsplit2_kernel<<<dim3(N2_ / 32, C2_ / 32, B_), dim3(32, 8)>>>(feats2);
    gemmP_kernel<<<dim3(N2_ / 64, O1_ / 128, B_), 256>>>();
    gemm1_kernel<<<dim3(N1_ / 64, O1_ / 128, B_), 256>>>();
    gemm2_kernel<<<dim3(N1_ / 64, O2_ / 128, B_), 256>>>(out);
}

// round 6
// speedup vs baseline: 1.9115x; 1.0875x over previous
#include <cuda_runtime.h>
#include <cuda_bf16.h>
#include <cstdint>

// ---- problem constants ----
#define B_    8
#define N1_   8192
#define N2_   2048
#define C1_   128
#define C2_   256
#define O1_   256
#define O2_   256

// ---- device scratch ----
__device__ __align__(16) __nv_bfloat16 g_W1a_hi[O1_ * C2_], g_W1a_lo[O1_ * C2_];
__device__ __align__(16) __nv_bfloat16 g_W1b_hi[O1_ * C1_], g_W1b_lo[O1_ * C1_];
__device__ __align__(16) __nv_bfloat16 g_W2_hi [O2_ * O1_], g_W2_lo [O2_ * O1_];
__device__ float g_b1eff[O1_], g_b2eff[O2_];
__device__ __align__(16) __nv_bfloat16 g_f1T_hi[(size_t)B_ * N1_ * C1_], g_f1T_lo[(size_t)B_ * N1_ * C1_];
__device__ __align__(16) __nv_bfloat16 g_f2T_hi[(size_t)B_ * N2_ * C2_], g_f2T_lo[(size_t)B_ * N2_ * C2_];
__device__ __align__(16) float g_PT[(size_t)B_ * N2_ * O1_];      // P^T [b][n2][o1]
__device__ int   g_idx[B_ * N1_ * 3];
__device__ float g_wgt[B_ * N1_ * 3];

// ============================================================
// portable tensor-core primitives
// ============================================================
__device__ __forceinline__ uint32_t smem_u32(const void* p) {
    uint32_t a;
    asm("{ .reg .u64 t; cvta.to.shared.u64 t, %1; cvt.u32.u64 %0, t; }" : "=r"(a) : "l"(p));
    return a;
}
__device__ __forceinline__ void ldsm4(uint32_t* r, uint32_t addr) {
    asm volatile("ldmatrix.sync.aligned.m8n8.x4.shared.b16 {%0,%1,%2,%3}, [%4];"
                 : "=r"(r[0]), "=r"(r[1]), "=r"(r[2]), "=r"(r[3]) : "r"(addr));
}
__device__ __forceinline__ void mma16816(float* c, const uint32_t* a, uint32_t b0, uint32_t b1) {
    asm volatile(
        "mma.sync.aligned.m16n8k16.row.col.f32.bf16.bf16.f32 "
        "{%0,%1,%2,%3}, {%4,%5,%6,%7}, {%8,%9}, {%0,%1,%2,%3};"
        : "+f"(c[0]), "+f"(c[1]), "+f"(c[2]), "+f"(c[3])
        : "r"(a[0]), "r"(a[1]), "r"(a[2]), "r"(a[3]), "r"(b0), "r"(b1));
}
// split-pack two floats -> bf16x2 hi word, bf16x2 lo word
__device__ __forceinline__ uint32_t splitpack(float a, float b, uint32_t& lo) {
    __nv_bfloat16 ha = __float2bfloat16(a), hb = __float2bfloat16(b);
    __nv_bfloat16 la = __float2bfloat16(a - __bfloat162float(ha));
    __nv_bfloat16 lb = __float2bfloat16(b - __bfloat162float(hb));
    __nv_bfloat162 H2; H2.x = ha; H2.y = hb;
    __nv_bfloat162 L2; L2.x = la; L2.y = lb;
    lo = *(uint32_t*)&L2;
    return *(uint32_t*)&H2;
}

// ============================================================
// FUSED gemm1+gemm2 kernel.
// Per CTA: 128 points. Stage1: h1[128pt][256 o1] = relu(f1T @ W1b^T + gather(PT) + b1)
// kept in smem (bf16 hi/lo). Stage2: out = relu(h1 @ W2^T + b2), A-frags straight
// from smem, output transposed through smem for coalesced stores.
// 512 threads = 16 warps (4M x 4N), warp tile 32(M) x 64(N).
// ============================================================
#define FSLD 40      // staging buffer pitch (bf16 el)
#define H1P  264     // h1 smem pitch (bf16 el)  -> 528B rows, conflict-free ldsm
#define OTP  132     // out-tile pitch (fp32 el) -> 528B rows, 16B-aligned
#define OF_AHI 0
#define OF_ALO 10240
#define OF_BHI 20480
#define OF_BLO 40960
#define OF_H1HI 61440
#define OF_H1LO 129024
#define OF_OUTT 61440          // aliases h1 region (h1 dead by then)
#define FSM_BYTES 196608

__global__ void __launch_bounds__(512, 1) fused12_kernel(float* __restrict__ out) {
    extern __shared__ __align__(16) char fsm[];
    __nv_bfloat16* sAhi = (__nv_bfloat16*)(fsm + OF_AHI);
    __nv_bfloat16* sAlo = (__nv_bfloat16*)(fsm + OF_ALO);
    __nv_bfloat16* sBhi = (__nv_bfloat16*)(fsm + OF_BHI);
    __nv_bfloat16* sBlo = (__nv_bfloat16*)(fsm + OF_BLO);
    __nv_bfloat16* h1hi = (__nv_bfloat16*)(fsm + OF_H1HI);
    __nv_bfloat16* h1lo = (__nv_bfloat16*)(fsm + OF_H1LO);
    float*         outT = (float*)(fsm + OF_OUTT);

    const int tid = threadIdx.x, lane = tid & 31, wid = tid >> 5;
    const int warpM = wid >> 2, warpN = wid & 3;
    const int b = blockIdx.y;
    const int pt0 = blockIdx.x * 128;

    const uint32_t sAhiB = smem_u32(sAhi), sAloB = smem_u32(sAlo);
    const uint32_t sBhiB = smem_u32(sBhi), sBloB = smem_u32(sBlo);
    const uint32_t h1hiB = smem_u32(h1hi), h1loB = smem_u32(h1lo);

    const int lrow = tid >> 2;          // 0..127
    const int lcol = (tid & 3) * 8;     // 0,8,16,24

    // fragment address components
    const uint32_t aRowSel = lane & 15;
    const uint32_t aColSel = (lane >> 4) << 3;
    const uint32_t bRow = ((lane >> 4) << 3) + (lane & 7);
    const uint32_t bCol = ((lane >> 3) & 1) << 3;

    // ---------------- stage 1 ----------------
    const __nv_bfloat16* Ah = g_f1T_hi + ((size_t)b * N1_ + pt0 + lrow) * C1_ + lcol;
    const __nv_bfloat16* Al = g_f1T_lo + ((size_t)b * N1_ + pt0 + lrow) * C1_ + lcol;
    const __nv_bfloat16* B1h0 = g_W1b_hi + (size_t)lrow * C1_ + lcol;
    const __nv_bfloat16* B1h1 = g_W1b_hi + (size_t)(lrow + 128) * C1_ + lcol;
    const __nv_bfloat16* B1l0 = g_W1b_lo + (size_t)lrow * C1_ + lcol;
    const __nv_bfloat16* B1l1 = g_W1b_lo + (size_t)(lrow + 128) * C1_ + lcol;

    float acc[2][8][4];
    #pragma unroll
    for (int i = 0; i < 2; i++)
        #pragma unroll
        for (int j = 0; j < 8; j++)
            #pragma unroll
            for (int k = 0; k < 4; k++) acc[i][j][k] = 0.f;

    uint4 rA0 = *(const uint4*)Ah,   rA1 = *(const uint4*)Al;
    uint4 rB0 = *(const uint4*)B1h0, rB1 = *(const uint4*)B1h1;
    uint4 rB2 = *(const uint4*)B1l0, rB3 = *(const uint4*)B1l1;

    for (int kb = 0; kb < C1_; kb += 32) {
        *(uint4*)&sAhi[lrow * FSLD + lcol] = rA0;
        *(uint4*)&sAlo[lrow * FSLD + lcol] = rA1;
        *(uint4*)&sBhi[lrow * FSLD + lcol] = rB0;
        *(uint4*)&sBhi[(lrow + 128) * FSLD + lcol] = rB1;
        *(uint4*)&sBlo[lrow * FSLD + lcol] = rB2;
        *(uint4*)&sBlo[(lrow + 128) * FSLD + lcol] = rB3;
        __syncthreads();

        int nk = (kb + 32 < C1_) ? kb + 32 : 0;
        rA0 = *(const uint4*)(Ah + nk);   rA1 = *(const uint4*)(Al + nk);
        rB0 = *(const uint4*)(B1h0 + nk); rB1 = *(const uint4*)(B1h1 + nk);
        rB2 = *(const uint4*)(B1l0 + nk); rB3 = *(const uint4*)(B1l1 + nk);

        #pragma unroll
        for (int ks = 0; ks < 2; ks++) {
            uint32_t ah[2][4], al[2][4];
            #pragma unroll
            for (int mi = 0; mi < 2; mi++) {
                uint32_t off = ((warpM * 32 + mi * 16 + aRowSel) * FSLD + ks * 16 + aColSel) * 2;
                ldsm4(ah[mi], sAhiB + off);
                ldsm4(al[mi], sAloB + off);
            }
            #pragma unroll
            for (int nj = 0; nj < 4; nj++) {
                uint32_t bh[4], bl[4];
                uint32_t off = ((warpN * 64 + nj * 16 + bRow) * FSLD + ks * 16 + bCol) * 2;
                ldsm4(bh, sBhiB + off);
                ldsm4(bl, sBloB + off);
                #pragma unroll
                for (int mi = 0; mi < 2; mi++)
                    #pragma unroll
                    for (int sub = 0; sub < 2; sub++) {
                        int ni = nj * 2 + sub;
                        uint32_t b0 = bh[sub * 2], b1 = bh[sub * 2 + 1];
                        uint32_t c0_ = bl[sub * 2], c1_ = bl[sub * 2 + 1];
                        mma16816(acc[mi][ni], ah[mi], b0, b1);   // hi*hi
                        mma16816(acc[mi][ni], ah[mi], c0_, c1_); // hi*lo
                        mma16816(acc[mi][ni], al[mi], b0, b1);   // lo*hi
                    }
            }
        }
        __syncthreads();
    }

    // prefetch stage-2 B chunk 0 (W2) while doing the gather epilogue
    const __nv_bfloat16* B2h0 = g_W2_hi + (size_t)lrow * O1_ + lcol;
    const __nv_bfloat16* B2h1 = g_W2_hi + (size_t)(lrow + 128) * O1_ + lcol;
    const __nv_bfloat16* B2l0 = g_W2_lo + (size_t)lrow * O1_ + lcol;
    const __nv_bfloat16* B2l1 = g_W2_lo + (size_t)(lrow + 128) * O1_ + lcol;
    rB0 = *(const uint4*)B2h0; rB1 = *(const uint4*)B2h1;
    rB2 = *(const uint4*)B2l0; rB3 = *(const uint4*)B2l1;

    // ---------------- epilogue 1: gather + bias + relu -> h1 smem (split) ----------------
    {
        const int r0 = lane >> 2;
        const int c0 = (lane & 3) * 2;
        const int*   IX = g_idx + (size_t)b * N1_ * 3;
        const float* WG = g_wgt + (size_t)b * N1_ * 3;
        const float* PT = g_PT + (size_t)b * N2_ * O1_;
        #pragma unroll
        for (int mi = 0; mi < 2; mi++)
            #pragma unroll
            for (int h = 0; h < 2; h++) {
                int gmL = warpM * 32 + mi * 16 + r0 + h * 8;
                int n = pt0 + gmL;
                int i0 = IX[n * 3], i1 = IX[n * 3 + 1], i2 = IX[n * 3 + 2];
                float w0 = WG[n * 3], w1 = WG[n * 3 + 1], w2 = WG[n * 3 + 2];
                #pragma unroll
                for (int ni = 0; ni < 8; ni++) {
                    int gn = warpN * 64 + ni * 8 + c0;
                    float2 p0 = *(const float2*)&PT[(size_t)i0 * O1_ + gn];
                    float2 p1 = *(const float2*)&PT[(size_t)i1 * O1_ + gn];
                    float2 p2 = *(const float2*)&PT[(size_t)i2 * O1_ + gn];
                    float2 bs = *(const float2*)&g_b1eff[gn];
                    float v0 = acc[mi][ni][h * 2 + 0] + bs.x + w0 * p0.x + w1 * p1.x + w2 * p2.x;
                    float v1 = acc[mi][ni][h * 2 + 1] + bs.y + w0 * p0.y + w1 * p1.y + w2 * p2.y;
                    v0 = fmaxf(v0, 0.f); v1 = fmaxf(v1, 0.f);
                    uint32_t lo, hi = splitpack(v0, v1, lo);
                    *(uint32_t*)&h1hi[gmL * H1P + gn] = hi;
                    *(uint32_t*)&h1lo[gmL * H1P + gn] = lo;
                }
            }
    }
    __syncthreads();   // h1 visible to all warps

    // ---------------- stage 2: out = relu(h1 @ W2^T + b2) ----------------
    float acc2[2][8][4];
    #pragma unroll
    for (int i = 0; i < 2; i++)
        #pragma unroll
        for (int j = 0; j < 8; j++)
            #pragma unroll
            for (int k = 0; k < 4; k++) acc2[i][j][k] = 0.f;

    for (int kb = 0; kb < O1_; kb += 32) {
        *(uint4*)&sBhi[lrow * FSLD + lcol] = rB0;
        *(uint4*)&sBhi[(lrow + 128) * FSLD + lcol] = rB1;
        *(uint4*)&sBlo[lrow * FSLD + lcol] = rB2;
        *(uint4*)&sBlo[(lrow + 128) * FSLD + lcol] = rB3;
        __syncthreads();

        int nk = (kb + 32 < O1_) ? kb + 32 : 0;
        rB0 = *(const uint4*)(B2h0 + nk); rB1 = *(const uint4*)(B2h1 + nk);
        rB2 = *(const uint4*)(B2l0 + nk); rB3 = *(const uint4*)(B2l1 + nk);

        #pragma unroll
        for (int ks = 0; ks < 2; ks++) {
            uint32_t ah[2][4], al[2][4];
            #pragma unroll
            for (int mi = 0; mi < 2; mi++) {
                uint32_t off = ((warpM * 32 + mi * 16 + aRowSel) * H1P + kb + ks * 16 + aColSel) * 2;
                ldsm4(ah[mi], h1hiB + off);
                ldsm4(al[mi], h1loB + off);
            }
            #pragma unroll
            for (int nj = 0; nj < 4; nj++) {
                uint32_t bh[4], bl[4];
                uint32_t off = ((warpN * 64 + nj * 16 + bRow) * FSLD + ks * 16 + bCol) * 2;
                ldsm4(bh, sBhiB + off);
                ldsm4(bl, sBloB + off);
                #pragma unroll
                for (int mi = 0; mi < 2; mi++)
                    #pragma unroll
                    for (int sub = 0; sub < 2; sub++) {
                        int ni = nj * 2 + sub;
                        uint32_t b0 = bh[sub * 2], b1 = bh[sub * 2 + 1];
                        uint32_t c0_ = bl[sub * 2], c1_ = bl[sub * 2 + 1];
                        mma16816(acc2[mi][ni], ah[mi], b0, b1);
                        mma16816(acc2[mi][ni], ah[mi], c0_, c1_);
                        mma16816(acc2[mi][ni], al[mi], b0, b1);
                    }
            }
        }
        __syncthreads();
    }

    // ---------------- epilogue 2: transpose through smem, coalesced store ----------------
    {
        const int r0 = lane >> 2;
        const int c0 = (lane & 3) * 2;
        #pragma unroll
        for (int mi = 0; mi < 2; mi++)
            #pragma unroll
            for (int h = 0; h < 2; h++) {
                int gmL = warpM * 32 + mi * 16 + r0 + h * 8;
                #pragma unroll
                for (int ni = 0; ni < 8; ni++) {
                    int gn = warpN * 64 + ni * 8 + c0;
                    float2 bs = *(const float2*)&g_b2eff[gn];
                    outT[(size_t)gn * OTP + gmL]       = fmaxf(acc2[mi][ni][h * 2 + 0] + bs.x, 0.f);
                    outT[(size_t)(gn + 1) * OTP + gmL] = fmaxf(acc2[mi][ni][h * 2 + 1] + bs.y, 0.f);
                }
            }
    }
    __syncthreads();

    float* dst = out + (size_t)b * O2_ * N1_ + pt0;
    for (int i = tid; i < 256 * 32; i += 512) {
        int o2 = i >> 5;
        int c = (i & 31) << 2;
        uint4 v = *(uint4*)&outT[o2 * OTP + c];
        *(uint4*)(dst + (size_t)o2 * N1_ + c) = v;
    }
}

// ============================================================
// gemmP: PT[b][n2][o1] = (f2T @ W1a^T)  — verified R5 core, EPI0 only.
// 256 threads = 8 warps (2M x 4N), tile 64(M=n2) x 128(N=o1), K=256.
// ============================================================
__global__ void __launch_bounds__(256, 2) gemmP_kernel() {
    __shared__ __align__(16) __nv_bfloat16 sAhi[64][FSLD],  sAlo[64][FSLD];
    __shared__ __align__(16) __nv_bfloat16 sBhi[128][FSLD], sBlo[128][FSLD];

    const int tid = threadIdx.x, lane = tid & 31, wid = tid >> 5;
    const int warpM = wid >> 2, warpN = wid & 3;
    const int b = blockIdx.z;
    const int Mbase = blockIdx.x * 64, Nbase = blockIdx.y * 128;

    float acc[2][4][4];
    #pragma unroll
    for (int i = 0; i < 2; i++)
        #pragma unroll
        for (int j = 0; j < 4; j++)
            #pragma unroll
            for (int k = 0; k < 4; k++) acc[i][j][k] = 0.f;

    const int lrow = tid >> 2;          // 0..63
    const int lcol = (tid & 3) * 8;

    const __nv_bfloat16* pAhi = g_f2T_hi + ((size_t)b * N2_ + Mbase + lrow) * C2_ + lcol;
    const __nv_bfloat16* pAlo = g_f2T_lo + ((size_t)b * N2_ + Mbase + lrow) * C2_ + lcol;
    const __nv_bfloat16* pBhi0 = g_W1a_hi + (size_t)(Nbase + lrow) * C2_ + lcol;
    const __nv_bfloat16* pBlo0 = g_W1a_lo + (size_t)(Nbase + lrow) * C2_ + lcol;
    const __nv_bfloat16* pBhi1 = g_W1a_hi + (size_t)(Nbase + lrow + 64) * C2_ + lcol;
    const __nv_bfloat16* pBlo1 = g_W1a_lo + (size_t)(Nbase + lrow + 64) * C2_ + lcol;

    const uint32_t aRowA = warpM * 32 + (lane & 15);
    const uint32_t aColA = (lane >> 4) << 3;
    const uint32_t bRowB = warpN * 32 + ((lane >> 4) << 3) + (lane & 7);
    const uint32_t bColB = ((lane >> 3) & 1) << 3;
    const uint32_t sAhiB = smem_u32(&sAhi[0][0]), sAloB = smem_u32(&sAlo[0][0]);
    const uint32_t sBhiB = smem_u32(&sBhi[0][0]), sBloB = smem_u32(&sBlo[0][0]);

    uint4 rA0 = *(const uint4*)pAhi,  rA1 = *(const uint4*)pAlo;
    uint4 rBh0 = *(const uint4*)pBhi0, rBh1 = *(const uint4*)pBhi1;
    uint4 rBl0 = *(const uint4*)pBlo0, rBl1 = *(const uint4*)pBlo1;

    for (int kb = 0; kb < C2_; kb += 32) {
        *(uint4*)&sAhi[lrow][lcol] = rA0;
        *(uint4*)&sAlo[lrow][lcol] = rA1;
        *(uint4*)&sBhi[lrow][lcol] = rBh0;
        *(uint4*)&sBhi[lrow + 64][lcol] = rBh1;
        *(uint4*)&sBlo[lrow][lcol] = rBl0;
        *(uint4*)&sBlo[lrow + 64][lcol] = rBl1;
        __syncthreads();

        int nk = (kb + 32 < C2_) ? kb + 32 : 0;
        rA0 = *(const uint4*)(pAhi + nk);  rA1 = *(const uint4*)(pAlo + nk);
        rBh0 = *(const uint4*)(pBhi0 + nk); rBh1 = *(const uint4*)(pBhi1 + nk);
        rBl0 = *(const uint4*)(pBlo0 + nk); rBl1 = *(const uint4*)(pBlo1 + nk);

        #pragma unroll
        for (int ks = 0; ks < 2; ks++) {
            uint32_t ah[2][4], al[2][4], bh[2][4], bl[2][4];
            #pragma unroll
            for (int mi = 0; mi < 2; mi++) {
                uint32_t off = ((aRowA + mi * 16) * FSLD + ks * 16 + aColA) * 2;
                ldsm4(ah[mi], sAhiB + off);
                ldsm4(al[mi], sAloB + off);
            }
            #pragma unroll
            for (int nj = 0; nj < 2; nj++) {
                uint32_t off = ((bRowB + nj * 16) * FSLD + ks * 16 + bColB) * 2;
                ldsm4(bh[nj], sBhiB + off);
                ldsm4(bl[nj], sBloB + off);
            }
            #pragma unroll
            for (int mi = 0; mi < 2; mi++)
                #pragma unroll
                for (int ni = 0; ni < 4; ni++) {
                    const uint32_t* BH = bh[ni >> 1];
                    const uint32_t* BL = bl[ni >> 1];
                    uint32_t b0 = BH[(ni & 1) * 2], b1 = BH[(ni & 1) * 2 + 1];
                    uint32_t c0_ = BL[(ni & 1) * 2], c1_ = BL[(ni & 1) * 2 + 1];
                    mma16816(acc[mi][ni], ah[mi], b0, b1);
                    mma16816(acc[mi][ni], ah[mi], c0_, c1_);
                    mma16816(acc[mi][ni], al[mi], b0, b1);
                }
        }
        __syncthreads();
    }

    const int r0 = lane >> 2;
    const int c0 = (lane & 3) * 2;
    float* outP = g_PT + (size_t)b * N2_ * O1_;
    #pragma unroll
    for (int mi = 0; mi < 2; mi++)
        #pragma unroll
        for (int h = 0; h < 2; h++) {
            int gm = Mbase + warpM * 32 + mi * 16 + r0 + h * 8;
            #pragma unroll
            for (int ni = 0; ni < 4; ni++) {
                int gn = Nbase + warpN * 32 + ni * 8 + c0;
                *(float2*)&outP[(size_t)gm * O1_ + gn] =
                    make_float2(acc[mi][ni][h * 2], acc[mi][ni][h * 2 + 1]);
            }
        }
}

// ============================================================
// prep: fold BN into W/b, split weights into bf16 hi/lo
// ============================================================
__global__ void prep_kernel(const float* __restrict__ W1, const float* __restrict__ b1,
                            const float* __restrict__ g1, const float* __restrict__ be1,
                            const float* __restrict__ W2, const float* __restrict__ b2,
                            const float* __restrict__ g2, const float* __restrict__ be2) {
    const float rs = 0.99999500003749969f;  // 1/sqrt(1+1e-5)
    int t = blockIdx.x * blockDim.x + threadIdx.x;
    int nt = gridDim.x * blockDim.x;
    for (int i = t; i < O1_ * C2_; i += nt) {
        int o = i / C2_;
        float w = W1[o * (C1_ + C2_) + (i % C2_)] * g1[o] * rs;
        __nv_bfloat16 hi = __float2bfloat16(w);
        g_W1a_hi[i] = hi;
        g_W1a_lo[i] = __float2bfloat16(w - __bfloat162float(hi));
    }
    for (int i = t; i < O1_ * C1_; i += nt) {
        int o = i / C1_;
        float w = W1[o * (C1_ + C2_) + C2_ + (i % C1_)] * g1[o] * rs;
        __nv_bfloat16 hi = __float2bfloat16(w);
        g_W1b_hi[i] = hi;
        g_W1b_lo[i] = __float2bfloat16(w - __bfloat162float(hi));
    }
    for (int i = t; i < O2_ * O1_; i += nt) {
        int o = i / O1_;
        float w = W2[i] * g2[o] * rs;
        __nv_bfloat16 hi = __float2bfloat16(w);
        g_W2_hi[i] = hi;
        g_W2_lo[i] = __float2bfloat16(w - __bfloat162float(hi));
    }
    for (int i = t; i < O1_; i += nt) g_b1eff[i] = g1[i] * rs * b1[i] + be1[i];
    for (int i = t; i < O2_; i += nt) g_b2eff[i] = g2[i] * rs * b2[i] + be2[i];
}

// ============================================================
// kNN: float4-packed candidates (1 LDS.128 per candidate)
// ============================================================
__global__ void __launch_bounds__(256) knn_kernel(const float* __restrict__ xyz1,
                                                  const float* __restrict__ xyz2) {
    __shared__ __align__(16) float4 s2[N2_];
    int b = blockIdx.y;
    const float* q = xyz2 + (size_t)b * N2_ * 3;
    for (int i = threadIdx.x; i < N2_; i += 256) {
        float ax = q[i * 3 + 0], ay = q[i * 3 + 1], az = q[i * 3 + 2];
        s2[i] = make_float4(ax, ay, az, ax * ax + ay * ay + az * az);
    }
    __syncthreads();

    int p = blockIdx.x * 256 + threadIdx.x;
    const float* pp = xyz1 + ((size_t)b * N1_ + p) * 3;
    float x = pp[0], y = pp[1], z = pp[2];
    float p2 = x * x + y * y + z * z;

    float d0 = 3.4e38f, d1 = 3.4e38f, d2 = 3.4e38f;
    int   j0 = 0, j1 = 0, j2 = 0;
    #pragma unroll 4
    for (int m = 0; m < N2_; m++) {
        float4 v = s2[m];
        float dot = x * v.x + y * v.y + z * v.z;
        float dd  = (p2 + v.w) - 2.0f * dot;
        if (dd < d2) {
            if (dd < d1) {
                d2 = d1; j2 = j1;
                if (dd < d0) { d1 = d0; j1 = j0; d0 = dd; j0 = m; }
                else         { d1 = dd; j1 = m; }
            } else { d2 = dd; j2 = m; }
        }
    }
    float r0 = sqrtf(fmaxf(d0, 0.f));
    float r1 = sqrtf(fmaxf(d1, 0.f));
    float r2 = sqrtf(fmaxf(d2, 0.f));
    float w0 = 1.0f / fmaxf(r0, 1e-8f);
    float w1 = 1.0f / fmaxf(r1, 1e-8f);
    float w2 = 1.0f / fmaxf(r2, 1e-8f);
    float inv = 1.0f / (w0 + w1 + w2);

    size_t base = ((size_t)b * N1_ + p) * 3;
    g_idx[base + 0] = j0; g_idx[base + 1] = j1; g_idx[base + 2] = j2;
    g_wgt[base + 0] = w0 * inv; g_wgt[base + 1] = w1 * inv; g_wgt[base + 2] = w2 * inv;
}

// ============================================================
// transpose + hi/lo split:  src[b][C][Np] -> dst[b][Np][C] (bf16 hi/lo)
// ============================================================
__device__ __forceinline__ void tsplit_body(const float* __restrict__ src,
                                            __nv_bfloat16* __restrict__ dhi,
                                            __nv_bfloat16* __restrict__ dlo,
                                            int C, int Np) {
    __shared__ float t[32][33];
    int n0 = blockIdx.x * 32, c0 = blockIdx.y * 32, b = blockIdx.z;
    int tx = threadIdx.x, ty = threadIdx.y;
    #pragma unroll
    for (int r = 0; r < 4; r++) {
        int c = c0 + ty + r * 8;
        t[ty + r * 8][tx] = src[((size_t)b * C + c) * Np + n0 + tx];
    }
    __syncthreads();
    #pragma unroll
    for (int r = 0; r < 4; r++) {
        int n = n0 + ty + r * 8;
        int c = c0 + tx;
        float v = t[tx][ty + r * 8];
        __nv_bfloat16 hi = __float2bfloat16(v);
        size_t o = ((size_t)b * Np + n) * C + c;
        dhi[o] = hi;
        dlo[o] = __float2bfloat16(v - __bfloat162float(hi));
    }
}
__global__ void tsplit1_kernel(const float* __restrict__ feats1) {
    tsplit_body(feats1, g_f1T_hi, g_f1T_lo, C1_, N1_);
}
__global__ void tsplit2_kernel(const float* __restrict__ feats2) {
    tsplit_body(feats2, g_f2T_hi, g_f2T_lo, C2_, N2_);
}

// ============================================================
extern "C" void kernel_launch(void* const* d_in, const int* in_sizes, int n_in,
                              void* d_out, int out_size) {
    const float* xyz1   = (const float*)d_in[0];
    const float* xyz2   = (const float*)d_in[1];
    const float* feats1 = (const float*)d_in[2];
    const float* feats2 = (const float*)d_in[3];
    const float* W1     = (const float*)d_in[4];
    const float* b1     = (const float*)d_in[5];
    const float* g1     = (const float*)d_in[6];
    const float* be1    = (const float*)d_in[7];
    const float* W2     = (const float*)d_in[8];
    const float* b2     = (const float*)d_in[9];
    const float* g2     = (const float*)d_in[10];
    const float* be2    = (const float*)d_in[11];
    float* out = (float*)d_out;

    cudaFuncSetAttribute(fused12_kernel, cudaFuncAttributeMaxDynamicSharedMemorySize, FSM_BYTES);

    prep_kernel<<<64, 256>>>(W1, b1, g1, be1, W2, b2, g2, be2);
    knn_kernel<<<dim3(N1_ / 256, B_), 256>>>(xyz1, xyz2);
    tsplit1_kernel<<<dim3(N1_ / 32, C1_ / 32, B_), dim3(32, 8)>>>(feats1);
    tsplit2_kernel<<<dim3(N2_ / 32, C2_ / 32, B_), dim3(32, 8)>>>(feats2);
    gemmP_kernel<<<dim3(N2_ / 64, O1_ / 128, B_), 256>>>();
    fused12_kernel<<<dim3(N1_ / 128, B_), 512, FSM_BYTES>>>(out);
}